// round 1
// baseline (speedup 1.0000x reference)
#include <cuda_runtime.h>
#include <cstdint>

#define BATCH 2048
#define IN_DIM 1024
#define HID 32768
#define TOPK 32

typedef unsigned long long ull;

// Scratch (allocation-free rule: __device__ globals)
__device__ ull   g_sel[BATCH * TOPK];          // key = (f32 bits << 32) | (0xFFFFFFFF - idx)
__device__ float g_wdt[(size_t)HID * IN_DIM];  // W_dec transposed: [HID][IN_DIM]

// ---------- packed f32x2 helpers (sm_103a: FFMA2 = 2x fp32 FFMA throughput) ----------
__device__ __forceinline__ ull pack_dup(float a) {
    ull r;
    asm("mov.b64 %0, {%1, %1};" : "=l"(r) : "f"(a));
    return r;
}
__device__ __forceinline__ ull fma2(ull a, ull b, ull c) {
    ull d;
    asm("fma.rn.f32x2 %0, %1, %2, %3;" : "=l"(d) : "l"(a), "l"(b), "l"(c));
    return d;
}
__device__ __forceinline__ void unpack2(ull v, float& lo, float& hi) {
    asm("mov.b64 {%0, %1}, %2;" : "=f"(lo), "=f"(hi) : "l"(v));
}

// ============================================================================
// Kernel 1: encode GEMM  H[b][j] = relu( sum_k X[b][k]*W[j][k] + b_enc[j] )
// 128x128x16 tiles, 256 threads, 8x8 microtile, f32x2 packed FMA.
// Grid: (16 batch-tiles, 256 feature-tiles); x-major over batch so each W tile
// is reused by the 16 concurrent batch tiles and X (8MB) stays L2-resident.
// ============================================================================
__global__ __launch_bounds__(256, 2)
void encode_gemm(const float* __restrict__ X, const float* __restrict__ W,
                 const float* __restrict__ be, float* __restrict__ Hout) {
    __shared__ float As[16][128];
    __shared__ float Bs[16][128];

    const int by = blockIdx.x;   // batch tile   0..15
    const int bx = blockIdx.y;   // feature tile 0..255
    const int tid = threadIdx.x;
    const int tx = tid & 15;
    const int ty = tid >> 4;

    const float* Xp = X + (size_t)(by * 128) * IN_DIM;
    const float* Wp = W + (size_t)(bx * 128) * IN_DIM;

    const int lrow = tid >> 2;          // 0..63
    const int lcol = (tid & 3) << 2;    // 0,4,8,12

    ull acc[8][4];
#pragma unroll
    for (int i = 0; i < 8; i++)
#pragma unroll
        for (int j = 0; j < 4; j++) acc[i][j] = 0ull;

    for (int k0 = 0; k0 < IN_DIM; k0 += 16) {
        float4 a0 = *(const float4*)(Xp + (size_t)lrow * IN_DIM + k0 + lcol);
        float4 a1 = *(const float4*)(Xp + (size_t)(lrow + 64) * IN_DIM + k0 + lcol);
        float4 b0 = *(const float4*)(Wp + (size_t)lrow * IN_DIM + k0 + lcol);
        float4 b1 = *(const float4*)(Wp + (size_t)(lrow + 64) * IN_DIM + k0 + lcol);
        __syncthreads();
        As[lcol + 0][lrow] = a0.x; As[lcol + 1][lrow] = a0.y;
        As[lcol + 2][lrow] = a0.z; As[lcol + 3][lrow] = a0.w;
        As[lcol + 0][lrow + 64] = a1.x; As[lcol + 1][lrow + 64] = a1.y;
        As[lcol + 2][lrow + 64] = a1.z; As[lcol + 3][lrow + 64] = a1.w;
        Bs[lcol + 0][lrow] = b0.x; Bs[lcol + 1][lrow] = b0.y;
        Bs[lcol + 2][lrow] = b0.z; Bs[lcol + 3][lrow] = b0.w;
        Bs[lcol + 0][lrow + 64] = b1.x; Bs[lcol + 1][lrow + 64] = b1.y;
        Bs[lcol + 2][lrow + 64] = b1.z; Bs[lcol + 3][lrow + 64] = b1.w;
        __syncthreads();

#pragma unroll
        for (int kk = 0; kk < 16; kk++) {
            float4 af0 = *(const float4*)&As[kk][ty * 8];
            float4 af1 = *(const float4*)&As[kk][ty * 8 + 4];
            ulonglong2 bv0 = *(const ulonglong2*)&Bs[kk][tx * 8];
            ulonglong2 bv1 = *(const ulonglong2*)&Bs[kk][tx * 8 + 4];
            ull b2[4] = {bv0.x, bv0.y, bv1.x, bv1.y};
            float a[8] = {af0.x, af0.y, af0.z, af0.w, af1.x, af1.y, af1.z, af1.w};
#pragma unroll
            for (int i = 0; i < 8; i++) {
                ull a2 = pack_dup(a[i]);
#pragma unroll
                for (int j = 0; j < 4; j++) acc[i][j] = fma2(a2, b2[j], acc[i][j]);
            }
        }
    }

    // Epilogue: bias + relu + store
    const int col0 = bx * 128 + tx * 8;
    float bias[8];
#pragma unroll
    for (int j = 0; j < 8; j++) bias[j] = be[col0 + j];

#pragma unroll
    for (int i = 0; i < 8; i++) {
        const int row = by * 128 + ty * 8 + i;
        float o[8];
        unpack2(acc[i][0], o[0], o[1]);
        unpack2(acc[i][1], o[2], o[3]);
        unpack2(acc[i][2], o[4], o[5]);
        unpack2(acc[i][3], o[6], o[7]);
#pragma unroll
        for (int j = 0; j < 8; j++) o[j] = fmaxf(o[j] + bias[j], 0.0f);
        float* dst = Hout + (size_t)row * HID + col0;
        *(float4*)(dst)     = make_float4(o[0], o[1], o[2], o[3]);
        *(float4*)(dst + 4) = make_float4(o[4], o[5], o[6], o[7]);
    }
}

// ============================================================================
// Kernel 2: per-row top-32 select + mask-write.
// One block per batch row, 256 threads. Phase 1: each thread keeps a local
// top-32 (by key = valbits<<32 | ~idx, matching jax top_k tie semantics:
// larger value wins, then smaller index) over its 128 elements. Phase 2:
// 32 rounds of block argmax over the 8192 candidates in smem. Phase 3:
// zero the whole h row and scatter the 32 kept values back.
// ============================================================================
extern __shared__ ull cand[];  // 8192 keys = 64 KB dynamic smem

__global__ void topk_select(float* __restrict__ Hbuf) {
    const int b = blockIdx.x;
    const int tid = threadIdx.x;
    float* rowp = Hbuf + (size_t)b * HID;

    __shared__ ull warpbest[8];
    __shared__ ull s_best;
    __shared__ ull sel[TOPK];

    ull* mine = &cand[tid * 32];
#pragma unroll
    for (int s = 0; s < 32; s++) mine[s] = 0ull;
    ull curmin = 0ull;
    int minpos = 0;

    // Phase 1: local top-32 (coalesced float4 sweep)
    for (int t = 0; t < 32; t++) {
        const int j4 = tid + 256 * t;
        float4 v = *(const float4*)(rowp + (size_t)j4 * 4);
        const int jbase = j4 * 4;
        float vals[4] = {v.x, v.y, v.z, v.w};
#pragma unroll
        for (int c = 0; c < 4; c++) {
            ull key = ((ull)__float_as_uint(vals[c]) << 32) |
                      (ull)(0xFFFFFFFFu - (unsigned)(jbase + c));
            if (key > curmin) {
                mine[minpos] = key;
                curmin = mine[0]; minpos = 0;
#pragma unroll
                for (int s = 1; s < 32; s++)
                    if (mine[s] < curmin) { curmin = mine[s]; minpos = s; }
            }
        }
    }
    __syncthreads();

    // Phase 2: 32 rounds of block-wide argmax (keys are unique -> unique owner)
    for (int r = 0; r < TOPK; r++) {
        ull lbest = 0ull; int bpos = -1;
        for (int t = tid; t < 8192; t += 256) {
            ull v = cand[t];
            if (v > lbest) { lbest = v; bpos = t; }
        }
        ull rbest = lbest;
#pragma unroll
        for (int o = 16; o > 0; o >>= 1) {
            ull other = __shfl_down_sync(0xFFFFFFFFu, rbest, o);
            if (other > rbest) rbest = other;
        }
        if ((tid & 31) == 0) warpbest[tid >> 5] = rbest;
        __syncthreads();
        if (tid == 0) {
            ull m = warpbest[0];
#pragma unroll
            for (int w = 1; w < 8; w++) if (warpbest[w] > m) m = warpbest[w];
            s_best = m;
        }
        __syncthreads();
        ull gb = s_best;
        if (bpos >= 0 && lbest == gb) {   // unique owner
            cand[bpos] = 0ull;
            sel[r] = gb;
            g_sel[b * TOPK + r] = gb;
        }
        __syncthreads();
    }

    // Phase 3: zero the row, then scatter kept values
    for (int t = tid; t < HID / 4; t += 256)
        *(float4*)(rowp + (size_t)t * 4) = make_float4(0.f, 0.f, 0.f, 0.f);
    __syncthreads();
    if (tid < TOPK) {
        ull k = sel[tid];
        unsigned idx = 0xFFFFFFFFu - (unsigned)(k & 0xFFFFFFFFull);
        rowp[idx] = __uint_as_float((unsigned)(k >> 32));
    }
}

// ============================================================================
// Kernel 3: transpose W_dec [IN_DIM][HID] -> g_wdt [HID][IN_DIM]
// ============================================================================
__global__ void transpose_wdec(const float* __restrict__ Wd) {
    __shared__ float tile[32][33];
    const int j0 = blockIdx.x * 32;  // HID
    const int i0 = blockIdx.y * 32;  // IN_DIM
    const int tx = threadIdx.x;      // 32
    const int ty = threadIdx.y;      // 8
#pragma unroll
    for (int r = 0; r < 4; r++)
        tile[ty + r * 8][tx] = Wd[(size_t)(i0 + ty + r * 8) * HID + j0 + tx];
    __syncthreads();
#pragma unroll
    for (int r = 0; r < 4; r++)
        g_wdt[(size_t)(j0 + ty + r * 8) * IN_DIM + i0 + tx] = tile[tx][ty + r * 8];
}

// ============================================================================
// Kernel 4: sparse decode  x_hat[b][i] = b_dec[i] + sum_k val_k * WdT[idx_k][i]
// ============================================================================
__global__ void decode_kernel(const float* __restrict__ bd, float* __restrict__ Xhat) {
    __shared__ float svals[TOPK];
    __shared__ int   sidx[TOPK];
    const int b = blockIdx.x;
    const int tid = threadIdx.x;
    if (tid < TOPK) {
        ull k = g_sel[b * TOPK + tid];
        svals[tid] = __uint_as_float((unsigned)(k >> 32));
        sidx[tid]  = (int)(0xFFFFFFFFu - (unsigned)(k & 0xFFFFFFFFull));
    }
    __syncthreads();
    float acc[4] = {0.f, 0.f, 0.f, 0.f};
    for (int k = 0; k < TOPK; k++) {
        const float* wr = g_wdt + (size_t)sidx[k] * IN_DIM;
        const float v = svals[k];
#pragma unroll
        for (int t = 0; t < 4; t++) acc[t] += v * wr[tid + t * 256];
    }
#pragma unroll
    for (int t = 0; t < 4; t++)
        Xhat[(size_t)b * IN_DIM + tid + t * 256] = acc[t] + bd[tid + t * 256];
}

// ============================================================================
extern "C" void kernel_launch(void* const* d_in, const int* in_sizes, int n_in,
                              void* d_out, int out_size) {
    const float* x     = (const float*)d_in[0];  // [2048,1024]
    const float* W_enc = (const float*)d_in[1];  // [32768,1024]
    const float* b_enc = (const float*)d_in[2];  // [32768]
    const float* W_dec = (const float*)d_in[3];  // [1024,32768]
    const float* b_dec = (const float*)d_in[4];  // [1024]

    float* xhat = (float*)d_out;                              // [2048,1024]
    float* hbuf = (float*)d_out + (size_t)BATCH * IN_DIM;     // [2048,32768]

    cudaFuncSetAttribute(topk_select, cudaFuncAttributeMaxDynamicSharedMemorySize,
                         8192 * (int)sizeof(ull));

    encode_gemm<<<dim3(16, 256), 256>>>(x, W_enc, b_enc, hbuf);
    transpose_wdec<<<dim3(HID / 32, IN_DIM / 32), dim3(32, 8)>>>(W_dec);
    topk_select<<<BATCH, 256, 8192 * sizeof(ull)>>>(hbuf);
    decode_kernel<<<BATCH, 256>>>(b_dec, xhat);
}

// round 3
// speedup vs baseline: 4.0878x; 4.0878x over previous
#include <cuda_runtime.h>
#include <cuda_bf16.h>
#include <cstdint>

#define BATCH 2048
#define IN_DIM 1024
#define HID 32768
#define TOPK 32
#define NCAND 64

typedef unsigned long long ull;

// ---------------- device scratch (allocation-free rule) ----------------
__device__ __nv_bfloat16 g_xbf[(size_t)BATCH * IN_DIM];   // 4 MB
__device__ __nv_bfloat16 g_wbf[(size_t)HID * IN_DIM];     // 64 MB
__device__ float         g_wdt[(size_t)HID * IN_DIM];     // 128 MB  W_dec^T
__device__ ull           g_cand[(size_t)BATCH * NCAND];   // approx top-64 keys
__device__ ull           g_sel[(size_t)BATCH * TOPK];     // exact top-32 keys

// ---------------- PTX helpers (sm_80+ only: no 'a'-suffix features) --------
__device__ __forceinline__ uint32_t smem_u32(const void* p) {
    uint32_t a;
    asm("{ .reg .u64 t; cvta.to.shared.u64 t, %1; cvt.u32.u64 %0, t; }" : "=r"(a) : "l"(p));
    return a;
}
__device__ __forceinline__ void cp_async16(uint32_t saddr, const void* gptr) {
    asm volatile("cp.async.cg.shared.global [%0], [%1], 16;" :: "r"(saddr), "l"(gptr));
}
#define CP_COMMIT()  asm volatile("cp.async.commit_group;")
#define CP_WAIT(n)   asm volatile("cp.async.wait_group %0;" :: "n"(n))

__device__ __forceinline__ void ldsm_x4(uint32_t& r0, uint32_t& r1, uint32_t& r2,
                                        uint32_t& r3, uint32_t addr) {
    asm volatile("ldmatrix.sync.aligned.m8n8.x4.shared.b16 {%0,%1,%2,%3}, [%4];"
                 : "=r"(r0), "=r"(r1), "=r"(r2), "=r"(r3) : "r"(addr));
}
__device__ __forceinline__ void mma_bf16(float* d, const uint32_t* a, const uint32_t* b) {
    asm volatile(
        "mma.sync.aligned.m16n8k16.row.col.f32.bf16.bf16.f32 "
        "{%0,%1,%2,%3}, {%4,%5,%6,%7}, {%8,%9}, {%0,%1,%2,%3};"
        : "+f"(d[0]), "+f"(d[1]), "+f"(d[2]), "+f"(d[3])
        : "r"(a[0]), "r"(a[1]), "r"(a[2]), "r"(a[3]), "r"(b[0]), "r"(b[1]));
}

// ============================================================================
// Kernel 0: fp32 -> bf16 conversion
// ============================================================================
__global__ void f32_to_bf16(const float* __restrict__ s, __nv_bfloat16* __restrict__ d, int n8) {
    int i = blockIdx.x * 256 + threadIdx.x;
    if (i >= n8) return;
    const float4* s4 = (const float4*)s;
    float4 a = s4[2 * i], b = s4[2 * i + 1];
    __nv_bfloat162 h0 = __float22bfloat162_rn(make_float2(a.x, a.y));
    __nv_bfloat162 h1 = __float22bfloat162_rn(make_float2(a.z, a.w));
    __nv_bfloat162 h2 = __float22bfloat162_rn(make_float2(b.x, b.y));
    __nv_bfloat162 h3 = __float22bfloat162_rn(make_float2(b.z, b.w));
    uint4 o;
    o.x = *(uint32_t*)&h0; o.y = *(uint32_t*)&h1;
    o.z = *(uint32_t*)&h2; o.w = *(uint32_t*)&h3;
    ((uint4*)d)[i] = o;
}

// ============================================================================
// Kernel 1: approx encode GEMM, bf16 mma.sync (m16n8k16), fp32 accum.
// CTA tile 128x128, BK=32, 3-stage cp.async pipeline, 8 warps = 2(m) x 4(n),
// warp tile 64x32. Smem rows of 64B with 16B-chunk XOR swizzle
// (chunk' = chunk ^ ((row>>1)&3)) -> conflict-free ldmatrix + cp.async.
// H = relu(x @ W_enc^T + b_enc) written fp32.
// ============================================================================
#define STAGES 3
#define TILE_BYTES 8192   // 128 rows * 64 B

__global__ __launch_bounds__(256, 1)
void encode_mma(const float* __restrict__ be, float* __restrict__ Hout) {
    extern __shared__ char smem[];
    const int tid = threadIdx.x;
    const int wid = tid >> 5, lid = tid & 31;
    const int by = blockIdx.x;   // batch tile 0..15
    const int bx = blockIdx.y;   // hid tile   0..255

    const uint32_t aAs = smem_u32(smem);
    const uint32_t aBs = aAs + STAGES * TILE_BYTES;

    const __nv_bfloat16* Ag0 = g_xbf + (size_t)(by * 128) * IN_DIM;
    const __nv_bfloat16* Bg0 = g_wbf + (size_t)(bx * 128) * IN_DIM;

    const int wm = (wid >> 2) * 64;   // warp row offset in tile
    const int wn = (wid & 3) * 32;    // warp col offset in tile

    float d[4][4][4];
#pragma unroll
    for (int i = 0; i < 4; i++)
#pragma unroll
        for (int j = 0; j < 4; j++)
#pragma unroll
            for (int e = 0; e < 4; e++) d[i][j][e] = 0.f;

    // per-thread load coords (2 chunks of 16B per operand per stage)
    int id0 = tid, id1 = tid + 256;
    int r0_ = id0 >> 2, c0_ = id0 & 3;
    int r1_ = id1 >> 2, c1_ = id1 & 3;
    uint32_t so0 = (uint32_t)(r0_ * 64 + ((c0_ ^ ((r0_ >> 1) & 3)) << 4));
    uint32_t so1 = (uint32_t)(r1_ * 64 + ((c1_ ^ ((r1_ >> 1) & 3)) << 4));

#define LOAD_STAGE(s, kt) do {                                                  \
        const __nv_bfloat16* Ak = Ag0 + (kt) * 32;                              \
        const __nv_bfloat16* Bk = Bg0 + (kt) * 32;                              \
        uint32_t sa = aAs + (s) * TILE_BYTES, sb = aBs + (s) * TILE_BYTES;      \
        cp_async16(sa + so0, Ak + (size_t)r0_ * IN_DIM + c0_ * 8);              \
        cp_async16(sa + so1, Ak + (size_t)r1_ * IN_DIM + c1_ * 8);              \
        cp_async16(sb + so0, Bk + (size_t)r0_ * IN_DIM + c0_ * 8);              \
        cp_async16(sb + so1, Bk + (size_t)r1_ * IN_DIM + c1_ * 8);              \
    } while (0)

    LOAD_STAGE(0, 0); CP_COMMIT();
    LOAD_STAGE(1, 1); CP_COMMIT();

    const int lrA = lid & 15;          // A frag row within 16
    const int kcA = lid >> 4;          // A frag k-chunk selector
    const int lrB = (lid & 7) + ((lid >> 4) << 3);
    const int kcB = (lid >> 3) & 1;

    for (int kt = 0; kt < IN_DIM / 32; kt++) {
        if (kt + 2 < IN_DIM / 32) LOAD_STAGE((kt + 2) % STAGES, kt + 2);
        CP_COMMIT();
        CP_WAIT(2);
        __syncthreads();

        const uint32_t sa = aAs + (kt % STAGES) * TILE_BYTES;
        const uint32_t sb = aBs + (kt % STAGES) * TILE_BYTES;
#pragma unroll
        for (int ks = 0; ks < 2; ks++) {
            uint32_t a[4][4];
#pragma unroll
            for (int i = 0; i < 4; i++) {
                int r = wm + i * 16 + lrA;
                int kc = ks * 2 + kcA;
                ldsm_x4(a[i][0], a[i][1], a[i][2], a[i][3],
                        sa + r * 64 + ((kc ^ ((r >> 1) & 3)) << 4));
            }
            uint32_t b[4][2];
#pragma unroll
            for (int j2 = 0; j2 < 2; j2++) {
                int r = wn + j2 * 16 + lrB;
                int kc = ks * 2 + kcB;
                uint32_t t0, t1, t2, t3;
                ldsm_x4(t0, t1, t2, t3, sb + r * 64 + ((kc ^ ((r >> 1) & 3)) << 4));
                b[2 * j2][0] = t0; b[2 * j2][1] = t1;
                b[2 * j2 + 1][0] = t2; b[2 * j2 + 1][1] = t3;
            }
#pragma unroll
            for (int i = 0; i < 4; i++)
#pragma unroll
                for (int j = 0; j < 4; j++) mma_bf16(d[i][j], a[i], b[j]);
        }
        __syncthreads();
    }

    // Epilogue: bias + relu + fp32 store
    const int gid = lid >> 2, tig = lid & 3;
#pragma unroll
    for (int i = 0; i < 4; i++) {
        const int row0 = by * 128 + wm + i * 16 + gid;
#pragma unroll
        for (int j = 0; j < 4; j++) {
            const int col = bx * 128 + wn + j * 8 + tig * 2;
            float b0 = be[col], b1 = be[col + 1];
            float2 v0, v1;
            v0.x = fmaxf(d[i][j][0] + b0, 0.f);
            v0.y = fmaxf(d[i][j][1] + b1, 0.f);
            v1.x = fmaxf(d[i][j][2] + b0, 0.f);
            v1.y = fmaxf(d[i][j][3] + b1, 0.f);
            *(float2*)(Hout + (size_t)row0 * HID + col) = v0;
            *(float2*)(Hout + (size_t)(row0 + 8) * HID + col) = v1;
        }
    }
}

// ============================================================================
// Kernel 2: approx top-64 candidate select per row (local top-12 + 64x argmax)
// ============================================================================
__global__ __launch_bounds__(256, 4) void topk64(const float* __restrict__ Hbuf) {
    const int b = blockIdx.x;
    const int tid = threadIdx.x;
    const float* rowp = Hbuf + (size_t)b * HID;

    __shared__ ull cand[256 * 12];
    __shared__ ull warpbest[8];
    __shared__ ull s_best;

    ull* mine = &cand[tid * 12];
#pragma unroll
    for (int s = 0; s < 12; s++) mine[s] = 0ull;
    ull curmin = 0ull;
    int minpos = 0;

    for (int t = 0; t < 32; t++) {
        const int j4 = tid + 256 * t;
        float4 v = *(const float4*)(rowp + (size_t)j4 * 4);
        const int jbase = j4 * 4;
        float vals[4] = {v.x, v.y, v.z, v.w};
#pragma unroll
        for (int c = 0; c < 4; c++) {
            ull key = ((ull)__float_as_uint(vals[c]) << 32) |
                      (ull)(0xFFFFFFFFu - (unsigned)(jbase + c));
            if (key > curmin) {
                mine[minpos] = key;
                curmin = mine[0]; minpos = 0;
#pragma unroll
                for (int s = 1; s < 12; s++)
                    if (mine[s] < curmin) { curmin = mine[s]; minpos = s; }
            }
        }
    }
    __syncthreads();

    for (int r = 0; r < NCAND; r++) {
        ull lbest = 0ull; int bpos = -1;
#pragma unroll
        for (int u = 0; u < 12; u++) {
            int t = tid + 256 * u;
            ull v = cand[t];
            if (v > lbest) { lbest = v; bpos = t; }
        }
        ull rbest = lbest;
#pragma unroll
        for (int o = 16; o > 0; o >>= 1) {
            ull other = __shfl_down_sync(0xFFFFFFFFu, rbest, o);
            if (other > rbest) rbest = other;
        }
        if ((tid & 31) == 0) warpbest[tid >> 5] = rbest;
        __syncthreads();
        if (tid == 0) {
            ull m = warpbest[0];
#pragma unroll
            for (int w = 1; w < 8; w++) if (warpbest[w] > m) m = warpbest[w];
            s_best = m;
        }
        __syncthreads();
        ull gb = s_best;
        if (bpos >= 0 && lbest == gb) {   // unique owner (keys unique by idx)
            cand[bpos] = 0ull;
            g_cand[b * NCAND + r] = gb;
        }
        __syncthreads();
    }
}

// ============================================================================
// Kernel 3: exact fp32 rescore of 64 candidates -> exact top-32 -> h scatter
// ============================================================================
__global__ __launch_bounds__(256, 4) void rescore(const float* __restrict__ X,
                                                  const float* __restrict__ W,
                                                  const float* __restrict__ be,
                                                  float* __restrict__ Hbuf) {
    const int b = blockIdx.x;
    const int tid = threadIdx.x;
    const int wid = tid >> 5, lid = tid & 31;

    __shared__ float xs[IN_DIM];
    __shared__ ull keys[NCAND];
    __shared__ ull ssel[TOPK];

    ((float4*)xs)[tid] = ((const float4*)(X + (size_t)b * IN_DIM))[tid];
    __syncthreads();

    for (int c = wid; c < NCAND; c += 8) {
        int f = (int)(0xFFFFFFFFu - (unsigned)(g_cand[b * NCAND + c] & 0xFFFFFFFFull));
        const float4* wr = (const float4*)(W + (size_t)f * IN_DIM);
        float acc = 0.f;
#pragma unroll
        for (int t = 0; t < 8; t++) {
            float4 w4 = wr[lid + t * 32];
            float4 x4 = ((const float4*)xs)[lid + t * 32];
            acc += w4.x * x4.x + w4.y * x4.y + w4.z * x4.z + w4.w * x4.w;
        }
#pragma unroll
        for (int o = 16; o > 0; o >>= 1) acc += __shfl_down_sync(0xFFFFFFFFu, acc, o);
        if (lid == 0) {
            float v = fmaxf(acc + be[f], 0.f);
            keys[c] = ((ull)__float_as_uint(v) << 32) | (ull)(0xFFFFFFFFu - (unsigned)f);
        }
    }
    __syncthreads();

    if (tid < NCAND) {
        ull k = keys[tid];
        int rank = 0;
#pragma unroll
        for (int j = 0; j < NCAND; j++) rank += (keys[j] > k);
        if (rank < TOPK) { ssel[rank] = k; g_sel[b * TOPK + rank] = k; }
    }
    __syncthreads();

    float4* row4 = (float4*)(Hbuf + (size_t)b * HID);
    const float4 z = make_float4(0.f, 0.f, 0.f, 0.f);
    for (int t = tid; t < HID / 4; t += 256) row4[t] = z;
    __syncthreads();
    if (tid < TOPK) {
        ull k = ssel[tid];
        unsigned idx = 0xFFFFFFFFu - (unsigned)(k & 0xFFFFFFFFull);
        Hbuf[(size_t)b * HID + idx] = __uint_as_float((unsigned)(k >> 32));
    }
}

// ============================================================================
// Kernel 4: transpose W_dec [IN_DIM][HID] -> g_wdt [HID][IN_DIM]
// ============================================================================
__global__ void transpose_wdec(const float* __restrict__ Wd) {
    __shared__ float tile[32][33];
    const int j0 = blockIdx.x * 32;
    const int i0 = blockIdx.y * 32;
    const int tx = threadIdx.x;
    const int ty = threadIdx.y;
#pragma unroll
    for (int r = 0; r < 4; r++)
        tile[ty + r * 8][tx] = Wd[(size_t)(i0 + ty + r * 8) * HID + j0 + tx];
    __syncthreads();
#pragma unroll
    for (int r = 0; r < 4; r++)
        g_wdt[(size_t)(j0 + ty + r * 8) * IN_DIM + i0 + tx] = tile[tx][ty + r * 8];
}

// ============================================================================
// Kernel 5: sparse decode
// ============================================================================
__global__ void decode_kernel(const float* __restrict__ bd, float* __restrict__ Xhat) {
    __shared__ float svals[TOPK];
    __shared__ int   sidx[TOPK];
    const int b = blockIdx.x;
    const int tid = threadIdx.x;
    if (tid < TOPK) {
        ull k = g_sel[b * TOPK + tid];
        svals[tid] = __uint_as_float((unsigned)(k >> 32));
        sidx[tid]  = (int)(0xFFFFFFFFu - (unsigned)(k & 0xFFFFFFFFull));
    }
    __syncthreads();
    float acc[4] = {0.f, 0.f, 0.f, 0.f};
    for (int k = 0; k < TOPK; k++) {
        const float* wr = g_wdt + (size_t)sidx[k] * IN_DIM;
        const float v = svals[k];
#pragma unroll
        for (int t = 0; t < 4; t++) acc[t] += v * wr[tid + t * 256];
    }
#pragma unroll
    for (int t = 0; t < 4; t++)
        Xhat[(size_t)b * IN_DIM + tid + t * 256] = acc[t] + bd[tid + t * 256];
}

// ============================================================================
extern "C" void kernel_launch(void* const* d_in, const int* in_sizes, int n_in,
                              void* d_out, int out_size) {
    const float* x     = (const float*)d_in[0];
    const float* W_enc = (const float*)d_in[1];
    const float* b_enc = (const float*)d_in[2];
    const float* W_dec = (const float*)d_in[3];
    const float* b_dec = (const float*)d_in[4];

    float* xhat = (float*)d_out;
    float* hbuf = (float*)d_out + (size_t)BATCH * IN_DIM;

    static __nv_bfloat16* xbf_p = nullptr;
    static __nv_bfloat16* wbf_p = nullptr;
    if (!xbf_p) cudaGetSymbolAddress((void**)&xbf_p, g_xbf);
    if (!wbf_p) cudaGetSymbolAddress((void**)&wbf_p, g_wbf);

    cudaFuncSetAttribute(encode_mma, cudaFuncAttributeMaxDynamicSharedMemorySize,
                         2 * STAGES * TILE_BYTES);

    const int nx8 = BATCH * IN_DIM / 8;
    const int nw8 = HID * IN_DIM / 8;
    f32_to_bf16<<<(nx8 + 255) / 256, 256>>>(x, xbf_p, nx8);
    f32_to_bf16<<<(nw8 + 255) / 256, 256>>>(W_enc, wbf_p, nw8);

    encode_mma<<<dim3(16, 256), 256, 2 * STAGES * TILE_BYTES>>>(b_enc, hbuf);
    transpose_wdec<<<dim3(HID / 32, IN_DIM / 32), dim3(32, 8)>>>(W_dec);
    topk64<<<BATCH, 256>>>(hbuf);
    rescore<<<BATCH, 256>>>(x, W_enc, b_enc, hbuf);
    decode_kernel<<<BATCH, 256>>>(b_dec, xhat);
}

// round 4
// speedup vs baseline: 4.3902x; 1.0740x over previous
#include <cuda_runtime.h>
#include <cuda_bf16.h>
#include <cstdint>

#define BATCH 2048
#define IN_DIM 1024
#define HID 32768
#define TOPK 32
#define NCAND 64

typedef unsigned long long ull;

// ---------------- device scratch (allocation-free rule) ----------------
__device__ __nv_bfloat16 g_xbf[(size_t)BATCH * IN_DIM];    // 4 MB
__device__ __nv_bfloat16 g_wbf[(size_t)HID * IN_DIM];      // 64 MB
__device__ __nv_bfloat16 g_happ[(size_t)BATCH * HID];      // 128 MB approx H
__device__ float         g_wdt[(size_t)HID * IN_DIM];      // 128 MB  W_dec^T
__device__ ull           g_cand[(size_t)BATCH * NCAND];    // approx top-64 keys
__device__ ull           g_sel[(size_t)BATCH * TOPK];      // exact top-32 keys

// ---------------- PTX helpers (sm_80+ only) ----------------
__device__ __forceinline__ uint32_t smem_u32(const void* p) {
    uint32_t a;
    asm("{ .reg .u64 t; cvta.to.shared.u64 t, %1; cvt.u32.u64 %0, t; }" : "=r"(a) : "l"(p));
    return a;
}
__device__ __forceinline__ void cp_async16(uint32_t saddr, const void* gptr) {
    asm volatile("cp.async.cg.shared.global [%0], [%1], 16;" :: "r"(saddr), "l"(gptr));
}
#define CP_COMMIT()  asm volatile("cp.async.commit_group;")
#define CP_WAIT(n)   asm volatile("cp.async.wait_group %0;" :: "n"(n))

__device__ __forceinline__ void ldsm_x4(uint32_t& r0, uint32_t& r1, uint32_t& r2,
                                        uint32_t& r3, uint32_t addr) {
    asm volatile("ldmatrix.sync.aligned.m8n8.x4.shared.b16 {%0,%1,%2,%3}, [%4];"
                 : "=r"(r0), "=r"(r1), "=r"(r2), "=r"(r3) : "r"(addr));
}
__device__ __forceinline__ void mma_bf16(float* d, const uint32_t* a, const uint32_t* b) {
    asm volatile(
        "mma.sync.aligned.m16n8k16.row.col.f32.bf16.bf16.f32 "
        "{%0,%1,%2,%3}, {%4,%5,%6,%7}, {%8,%9}, {%0,%1,%2,%3};"
        : "+f"(d[0]), "+f"(d[1]), "+f"(d[2]), "+f"(d[3])
        : "r"(a[0]), "r"(a[1]), "r"(a[2]), "r"(a[3]), "r"(b[0]), "r"(b[1]));
}

// ============================================================================
// Kernel 0: fp32 -> bf16 conversion
// ============================================================================
__global__ void f32_to_bf16(const float* __restrict__ s, __nv_bfloat16* __restrict__ d, int n8) {
    int i = blockIdx.x * 256 + threadIdx.x;
    if (i >= n8) return;
    const float4* s4 = (const float4*)s;
    float4 a = s4[2 * i], b = s4[2 * i + 1];
    __nv_bfloat162 h0 = __float22bfloat162_rn(make_float2(a.x, a.y));
    __nv_bfloat162 h1 = __float22bfloat162_rn(make_float2(a.z, a.w));
    __nv_bfloat162 h2 = __float22bfloat162_rn(make_float2(b.x, b.y));
    __nv_bfloat162 h3 = __float22bfloat162_rn(make_float2(b.z, b.w));
    uint4 o;
    o.x = *(uint32_t*)&h0; o.y = *(uint32_t*)&h1;
    o.z = *(uint32_t*)&h2; o.w = *(uint32_t*)&h3;
    ((uint4*)d)[i] = o;
}

// ============================================================================
// Kernel 1: approx encode GEMM, bf16 mma.sync, fp32 accum, bf16 H out.
// CTA tile 128(M batch) x 256(N hid), BK=32, 3-stage cp.async pipeline.
// 8 warps = 2(m) x 4(n), warp tile 64x64 -> 32 MMA per 8 LDSM per k16.
// Smem rows 64B, 16B-chunk XOR swizzle: chunk' = chunk ^ ((row>>1)&3).
// ============================================================================
#define STAGES 3
#define A_TILE 8192    // 128 * 64B
#define B_TILE 16384   // 256 * 64B
#define ENC_SMEM (STAGES * (A_TILE + B_TILE))

__global__ __launch_bounds__(256, 1)
void encode_mma(const float* __restrict__ be) {
    extern __shared__ char smem[];
    const int tid = threadIdx.x;
    const int wid = tid >> 5, lid = tid & 31;
    const int by = blockIdx.x;   // batch tile 0..15
    const int bx = blockIdx.y;   // hid tile   0..127

    const uint32_t aAs = smem_u32(smem);
    const uint32_t aBs = aAs + STAGES * A_TILE;

    const __nv_bfloat16* Ag0 = g_xbf + (size_t)(by * 128) * IN_DIM;
    const __nv_bfloat16* Bg0 = g_wbf + (size_t)(bx * 256) * IN_DIM;

    const int wm = (wid & 1) * 64;    // warp row offset
    const int wn = (wid >> 1) * 64;   // warp col offset

    float d[4][8][4];
#pragma unroll
    for (int i = 0; i < 4; i++)
#pragma unroll
        for (int j = 0; j < 8; j++)
#pragma unroll
            for (int e = 0; e < 4; e++) d[i][j][e] = 0.f;

    // per-thread cp.async coords: row rr(+64k), chunk cc; swizzle invariant mod 64 rows
    const int rr = tid >> 2, cc = tid & 3;
    const uint32_t so = (uint32_t)(rr * 64 + ((cc ^ ((rr >> 1) & 3)) << 4));
    const size_t go = (size_t)rr * IN_DIM + cc * 8;

#define LOAD_STAGE(s, kt) do {                                                   \
        const __nv_bfloat16* Ak = Ag0 + (kt) * 32;                               \
        const __nv_bfloat16* Bk = Bg0 + (kt) * 32;                               \
        uint32_t sa = aAs + (s) * A_TILE, sb = aBs + (s) * B_TILE;               \
        cp_async16(sa + so,               Ak + go);                              \
        cp_async16(sa + so + 64 * 64,     Ak + go + (size_t)64 * IN_DIM);        \
        cp_async16(sb + so,               Bk + go);                              \
        cp_async16(sb + so + 64 * 64,     Bk + go + (size_t)64 * IN_DIM);        \
        cp_async16(sb + so + 128 * 64,    Bk + go + (size_t)128 * IN_DIM);       \
        cp_async16(sb + so + 192 * 64,    Bk + go + (size_t)192 * IN_DIM);       \
    } while (0)

    LOAD_STAGE(0, 0); CP_COMMIT();
    LOAD_STAGE(1, 1); CP_COMMIT();

    const int lrA = lid & 15;
    const int kcA = lid >> 4;
    const int lrB = (lid & 7) + ((lid >> 4) << 3);
    const int kcB = (lid >> 3) & 1;

    for (int kt = 0; kt < IN_DIM / 32; kt++) {
        if (kt + 2 < IN_DIM / 32) LOAD_STAGE((kt + 2) % STAGES, kt + 2);
        CP_COMMIT();
        CP_WAIT(2);
        __syncthreads();

        const uint32_t sa = aAs + (kt % STAGES) * A_TILE;
        const uint32_t sb = aBs + (kt % STAGES) * B_TILE;
#pragma unroll
        for (int ks = 0; ks < 2; ks++) {
            uint32_t a[4][4];
#pragma unroll
            for (int i = 0; i < 4; i++) {
                int r = wm + i * 16 + lrA;
                int kc = ks * 2 + kcA;
                ldsm_x4(a[i][0], a[i][1], a[i][2], a[i][3],
                        sa + r * 64 + ((kc ^ ((r >> 1) & 3)) << 4));
            }
            uint32_t b[8][2];
#pragma unroll
            for (int j2 = 0; j2 < 4; j2++) {
                int r = wn + j2 * 16 + lrB;
                int kc = ks * 2 + kcB;
                uint32_t t0, t1, t2, t3;
                ldsm_x4(t0, t1, t2, t3, sb + r * 64 + ((kc ^ ((r >> 1) & 3)) << 4));
                b[2 * j2][0] = t0; b[2 * j2][1] = t1;
                b[2 * j2 + 1][0] = t2; b[2 * j2 + 1][1] = t3;
            }
#pragma unroll
            for (int i = 0; i < 4; i++)
#pragma unroll
                for (int j = 0; j < 8; j++) mma_bf16(d[i][j], a[i], b[j]);
        }
        __syncthreads();
    }

    // Epilogue: bias + relu -> bf16 H scratch
    const int gid = lid >> 2, tig = lid & 3;
    float b0[8], b1[8];
#pragma unroll
    for (int j = 0; j < 8; j++) {
        const int col = bx * 256 + wn + j * 8 + tig * 2;
        b0[j] = be[col]; b1[j] = be[col + 1];
    }
#pragma unroll
    for (int i = 0; i < 4; i++) {
        const int row0 = by * 128 + wm + i * 16 + gid;
        __nv_bfloat16* dst0 = g_happ + (size_t)row0 * HID + bx * 256 + wn + tig * 2;
        __nv_bfloat16* dst1 = dst0 + (size_t)8 * HID;
#pragma unroll
        for (int j = 0; j < 8; j++) {
            __nv_bfloat162 lo = __float22bfloat162_rn(
                make_float2(fmaxf(d[i][j][0] + b0[j], 0.f), fmaxf(d[i][j][1] + b1[j], 0.f)));
            __nv_bfloat162 hi = __float22bfloat162_rn(
                make_float2(fmaxf(d[i][j][2] + b0[j], 0.f), fmaxf(d[i][j][3] + b1[j], 0.f)));
            *(uint32_t*)(dst0 + j * 8) = *(uint32_t*)&lo;
            *(uint32_t*)(dst1 + j * 8) = *(uint32_t*)&hi;
        }
    }
}

// ============================================================================
// Kernel 2: approx top-64 candidate select per row, reading bf16 H.
// bf16 bits << 16 are exactly the fp32 bits (free conversion in the key).
// ============================================================================
__global__ __launch_bounds__(256, 4) void topk64() {
    const int b = blockIdx.x;
    const int tid = threadIdx.x;
    const uint4* rowp = (const uint4*)(g_happ + (size_t)b * HID);

    __shared__ ull cand[256 * 12];
    __shared__ ull warpbest[8];
    __shared__ ull s_best;

    ull* mine = &cand[tid * 12];
#pragma unroll
    for (int s = 0; s < 12; s++) mine[s] = 0ull;
    ull curmin = 0ull;
    int minpos = 0;

    for (int t = 0; t < 16; t++) {               // 16 uint4 = 128 bf16 per thread
        const int u8 = tid + 256 * t;
        uint4 v = rowp[u8];
        const int jbase = u8 * 8;
        uint32_t w[4] = {v.x, v.y, v.z, v.w};
#pragma unroll
        for (int c = 0; c < 4; c++) {
            uint32_t flo = w[c] << 16;
            uint32_t fhi = w[c] & 0xFFFF0000u;
            ull klo = ((ull)flo << 32) | (ull)(0xFFFFFFFFu - (unsigned)(jbase + 2 * c));
            ull khi = ((ull)fhi << 32) | (ull)(0xFFFFFFFFu - (unsigned)(jbase + 2 * c + 1));
#pragma unroll
            for (int h = 0; h < 2; h++) {
                ull key = h ? khi : klo;
                if (key > curmin) {
                    mine[minpos] = key;
                    curmin = mine[0]; minpos = 0;
#pragma unroll
                    for (int s = 1; s < 12; s++)
                        if (mine[s] < curmin) { curmin = mine[s]; minpos = s; }
                }
            }
        }
    }
    __syncthreads();

    for (int r = 0; r < NCAND; r++) {
        ull lbest = 0ull; int bpos = -1;
#pragma unroll
        for (int u = 0; u < 12; u++) {
            int t = tid + 256 * u;
            ull v = cand[t];
            if (v > lbest) { lbest = v; bpos = t; }
        }
        ull rbest = lbest;
#pragma unroll
        for (int o = 16; o > 0; o >>= 1) {
            ull other = __shfl_down_sync(0xFFFFFFFFu, rbest, o);
            if (other > rbest) rbest = other;
        }
        if ((tid & 31) == 0) warpbest[tid >> 5] = rbest;
        __syncthreads();
        if (tid == 0) {
            ull m = warpbest[0];
#pragma unroll
            for (int w = 1; w < 8; w++) if (warpbest[w] > m) m = warpbest[w];
            s_best = m;
        }
        __syncthreads();
        ull gb = s_best;
        if (bpos >= 0 && lbest == gb) {
            cand[bpos] = 0ull;
            g_cand[b * NCAND + r] = gb;
        }
        __syncthreads();
    }
}

// ============================================================================
// Kernel 3: exact fp32 rescore of 64 candidates -> exact top-32 -> h scatter
// ============================================================================
__global__ __launch_bounds__(256, 4) void rescore(const float* __restrict__ X,
                                                  const float* __restrict__ W,
                                                  const float* __restrict__ be,
                                                  float* __restrict__ Hbuf) {
    const int b = blockIdx.x;
    const int tid = threadIdx.x;
    const int wid = tid >> 5, lid = tid & 31;

    __shared__ float xs[IN_DIM];
    __shared__ ull keys[NCAND];
    __shared__ ull ssel[TOPK];

    ((float4*)xs)[tid] = ((const float4*)(X + (size_t)b * IN_DIM))[tid];
    __syncthreads();

    for (int c = wid; c < NCAND; c += 8) {
        int f = (int)(0xFFFFFFFFu - (unsigned)(g_cand[b * NCAND + c] & 0xFFFFFFFFull));
        const float4* wr = (const float4*)(W + (size_t)f * IN_DIM);
        float acc = 0.f;
#pragma unroll
        for (int t = 0; t < 8; t++) {
            float4 w4 = wr[lid + t * 32];
            float4 x4 = ((const float4*)xs)[lid + t * 32];
            acc += w4.x * x4.x + w4.y * x4.y + w4.z * x4.z + w4.w * x4.w;
        }
#pragma unroll
        for (int o = 16; o > 0; o >>= 1) acc += __shfl_down_sync(0xFFFFFFFFu, acc, o);
        if (lid == 0) {
            float v = fmaxf(acc + be[f], 0.f);
            keys[c] = ((ull)__float_as_uint(v) << 32) | (ull)(0xFFFFFFFFu - (unsigned)f);
        }
    }
    __syncthreads();

    if (tid < NCAND) {
        ull k = keys[tid];
        int rank = 0;
#pragma unroll
        for (int j = 0; j < NCAND; j++) rank += (keys[j] > k);
        if (rank < TOPK) { ssel[rank] = k; g_sel[b * TOPK + rank] = k; }
    }
    __syncthreads();

    float4* row4 = (float4*)(Hbuf + (size_t)b * HID);
    const float4 z = make_float4(0.f, 0.f, 0.f, 0.f);
    for (int t = tid; t < HID / 4; t += 256) row4[t] = z;
    __syncthreads();
    if (tid < TOPK) {
        ull k = ssel[tid];
        unsigned idx = 0xFFFFFFFFu - (unsigned)(k & 0xFFFFFFFFull);
        Hbuf[(size_t)b * HID + idx] = __uint_as_float((unsigned)(k >> 32));
    }
}

// ============================================================================
// Kernel 4: transpose W_dec [IN_DIM][HID] -> g_wdt [HID][IN_DIM]
// ============================================================================
__global__ void transpose_wdec(const float* __restrict__ Wd) {
    __shared__ float tile[32][33];
    const int j0 = blockIdx.x * 32;
    const int i0 = blockIdx.y * 32;
    const int tx = threadIdx.x;
    const int ty = threadIdx.y;
#pragma unroll
    for (int r = 0; r < 4; r++)
        tile[ty + r * 8][tx] = Wd[(size_t)(i0 + ty + r * 8) * HID + j0 + tx];
    __syncthreads();
#pragma unroll
    for (int r = 0; r < 4; r++)
        g_wdt[(size_t)(j0 + ty + r * 8) * IN_DIM + i0 + tx] = tile[tx][ty + r * 8];
}

// ============================================================================
// Kernel 5: sparse decode
// ============================================================================
__global__ void decode_kernel(const float* __restrict__ bd, float* __restrict__ Xhat) {
    __shared__ float svals[TOPK];
    __shared__ int   sidx[TOPK];
    const int b = blockIdx.x;
    const int tid = threadIdx.x;
    if (tid < TOPK) {
        ull k = g_sel[b * TOPK + tid];
        svals[tid] = __uint_as_float((unsigned)(k >> 32));
        sidx[tid]  = (int)(0xFFFFFFFFu - (unsigned)(k & 0xFFFFFFFFull));
    }
    __syncthreads();
    float acc[4] = {0.f, 0.f, 0.f, 0.f};
    for (int k = 0; k < TOPK; k++) {
        const float* wr = g_wdt + (size_t)sidx[k] * IN_DIM;
        const float v = svals[k];
#pragma unroll
        for (int t = 0; t < 4; t++) acc[t] += v * wr[tid + t * 256];
    }
#pragma unroll
    for (int t = 0; t < 4; t++)
        Xhat[(size_t)b * IN_DIM + tid + t * 256] = acc[t] + bd[tid + t * 256];
}

// ============================================================================
extern "C" void kernel_launch(void* const* d_in, const int* in_sizes, int n_in,
                              void* d_out, int out_size) {
    const float* x     = (const float*)d_in[0];
    const float* W_enc = (const float*)d_in[1];
    const float* b_enc = (const float*)d_in[2];
    const float* W_dec = (const float*)d_in[3];
    const float* b_dec = (const float*)d_in[4];

    float* xhat = (float*)d_out;
    float* hbuf = (float*)d_out + (size_t)BATCH * IN_DIM;

    static __nv_bfloat16* xbf_p = nullptr;
    static __nv_bfloat16* wbf_p = nullptr;
    if (!xbf_p) cudaGetSymbolAddress((void**)&xbf_p, g_xbf);
    if (!wbf_p) cudaGetSymbolAddress((void**)&wbf_p, g_wbf);

    cudaFuncSetAttribute(encode_mma, cudaFuncAttributeMaxDynamicSharedMemorySize, ENC_SMEM);

    const int nx8 = BATCH * IN_DIM / 8;
    const int nw8 = HID * IN_DIM / 8;
    f32_to_bf16<<<(nx8 + 255) / 256, 256>>>(x, xbf_p, nx8);
    f32_to_bf16<<<(nw8 + 255) / 256, 256>>>(W_enc, wbf_p, nw8);

    encode_mma<<<dim3(16, 128), 256, ENC_SMEM>>>(b_enc);
    transpose_wdec<<<dim3(HID / 32, IN_DIM / 32), dim3(32, 8)>>>(W_dec);
    topk64<<<BATCH, 256>>>();
    rescore<<<BATCH, 256>>>(x, W_enc, b_enc, hbuf);
    decode_kernel<<<BATCH, 256>>>(b_dec, xhat);
}